// round 15
// baseline (speedup 1.0000x reference)
#include <cuda_runtime.h>

// mailbox: [N=50000, DEG=32, FEAT=128] float32 -> out[n][f] = mean over deg.
//
// Pure HBM-bound stream, ~845MB, zero reuse. Converged design: one thread per
// (node, float4-col); warp = exactly one 512B neighbor row -> every LDG.128 a
// full coalesced line; fully-unrolled deg loop, MLP=32/thread.
// __ldcg: read-once stream, L2-only (measured best vs .cs/default).
//
// Knob trend: block 256 -> 512 gave -1.4% (123.7us, 87.5% DRAM). R15 pushes
// the same lever: block=1024 (occ 2, same 2048 thr/SM, 1563 blocks = fewer
// dispatch events, longer uninterrupted per-SM streams), 4 accum chains.

#define N_NODES 50000
#define MAX_DEG 32
#define FEAT4   32                      // 128 floats / 4
#define TOTAL4  (N_NODES * FEAT4)       // 1,600,000 float4 outputs

__global__ void __launch_bounds__(1024, 2)
mean_agg_kernel(const float4* __restrict__ mailbox, float4* __restrict__ out) {
    int idx = blockIdx.x * blockDim.x + threadIdx.x;   // n * FEAT4 + f4
    if (idx >= TOTAL4) return;

    int n  = idx >> 5;          // / FEAT4
    int f4 = idx & 31;          // % FEAT4

    const float4* p = mailbox + ((long long)n * (MAX_DEG * FEAT4)) + f4;

    // four independent accumulator chains
    float4 a0 = make_float4(0.f, 0.f, 0.f, 0.f);
    float4 a1 = make_float4(0.f, 0.f, 0.f, 0.f);
    float4 a2 = make_float4(0.f, 0.f, 0.f, 0.f);
    float4 a3 = make_float4(0.f, 0.f, 0.f, 0.f);
#pragma unroll
    for (int d = 0; d < MAX_DEG; d += 4) {
        float4 v0 = __ldcg(&p[(d + 0) * FEAT4]);
        float4 v1 = __ldcg(&p[(d + 1) * FEAT4]);
        float4 v2 = __ldcg(&p[(d + 2) * FEAT4]);
        float4 v3 = __ldcg(&p[(d + 3) * FEAT4]);
        a0.x += v0.x; a0.y += v0.y; a0.z += v0.z; a0.w += v0.w;
        a1.x += v1.x; a1.y += v1.y; a1.z += v1.z; a1.w += v1.w;
        a2.x += v2.x; a2.y += v2.y; a2.z += v2.z; a2.w += v2.w;
        a3.x += v3.x; a3.y += v3.y; a3.z += v3.z; a3.w += v3.w;
    }

    const float inv = 1.0f / (float)MAX_DEG;
    float4 acc;
    acc.x = ((a0.x + a1.x) + (a2.x + a3.x)) * inv;
    acc.y = ((a0.y + a1.y) + (a2.y + a3.y)) * inv;
    acc.z = ((a0.z + a1.z) + (a2.z + a3.z)) * inv;
    acc.w = ((a0.w + a1.w) + (a2.w + a3.w)) * inv;
    out[idx] = acc;
}

extern "C" void kernel_launch(void* const* d_in, const int* in_sizes, int n_in,
                              void* d_out, int out_size) {
    const float4* mailbox = (const float4*)d_in[0];
    float4* out = (float4*)d_out;
    const int threads = 1024;
    const int blocks = (TOTAL4 + threads - 1) / threads;  // 1563
    mean_agg_kernel<<<blocks, threads>>>(mailbox, out);
}